// round 2
// baseline (speedup 1.0000x reference)
#include <cuda_runtime.h>
#include <cstdint>

// Problem constants (fixed by the reference)
#define N_TOK  8192
#define DMODEL 1024
#define NEXP   8
#define HDIM   2816
#define CAP    1280                  // int(1.25 * 8192 / 8)
#define SLOTS  (NEXP * CAP)          // 10240

// -------- device scratch (no allocations allowed) --------
__device__ int   g_slot_of_token[N_TOK];       // slot id, or SLOTS if dropped
__device__ int   g_token_of_slot[SLOTS];       // -1 for empty slots
__device__ int   g_count[NEXP];                // tokens kept per expert (<= CAP)
__device__ float g_G  [(size_t)SLOTS * HDIM];  // gate pre-activation  (115 MB)
__device__ float g_ACT[(size_t)SLOTS * HDIM];  // silu(G) * U          (115 MB)
__device__ float g_Y  [(size_t)SLOTS * DMODEL];// down output          (40 MB)

// ---------------- routing: order-preserving per-expert scan ----------------
// One block, 8 warps; warp e scans all tokens with ballot/popc prefix counts.
// The index tensor may be int32 or int64 depending on how the reference was
// materialized (JAX without x64 silently downcasts jnp.int64 -> int32).
// Detect at runtime: view the buffer as 4-byte words; if ANY odd word among
// the first N_TOK words is nonzero, the buffer is int32 (values 0..7 at every
// word). If all odd words are zero, it is little-endian int64 (high words 0).
__global__ void route_kernel(const int* __restrict__ idxw) {
    __shared__ int s_any;
    int tid = threadIdx.x;
    if (tid == 0) s_any = 0;
    for (int s = tid; s < SLOTS; s += 256) g_token_of_slot[s] = -1;
    __syncthreads();

    int local = 0;
    for (int i = 2 * tid + 1; i < N_TOK; i += 512) local |= idxw[i];
    if (local) atomicOr(&s_any, 1);
    __syncthreads();
    const int stride = s_any ? 1 : 2;   // int32 -> 1 word/token, int64 -> 2

    int warp = tid >> 5, lane = tid & 31;
    if (warp < NEXP) {
        int e = warp;
        int cnt = 0;
        for (int base = 0; base < N_TOK; base += 32) {
            int t = base + lane;
            int ei = idxw[t * stride];
            bool m = (ei == e);
            unsigned mask = __ballot_sync(0xffffffffu, m);
            if (m) {
                int pos = cnt + __popc(mask & ((1u << lane) - 1u));
                if (pos < CAP) {
                    g_slot_of_token[t] = e * CAP + pos;
                    g_token_of_slot[e * CAP + pos] = t;
                } else {
                    g_slot_of_token[t] = SLOTS;  // dropped -> passthrough
                }
            }
            cnt += __popc(mask);
        }
        if (lane == 0) g_count[e] = (cnt < CAP) ? cnt : CAP;
    }
}

// ---------------- packed fp32x2 helpers (FFMA2 path, 2x fp32 tput) --------
__device__ __forceinline__ unsigned long long pack2(float lo, float hi) {
    unsigned long long r;
    asm("mov.b64 %0, {%1, %2};" : "=l"(r) : "f"(lo), "f"(hi));
    return r;
}
__device__ __forceinline__ void unpack2(unsigned long long v, float& lo, float& hi) {
    asm("mov.b64 {%0, %1}, %2;" : "=f"(lo), "=f"(hi) : "l"(v));
}
__device__ __forceinline__ void fma2(unsigned long long& d,
                                     unsigned long long a, unsigned long long b) {
    asm("fma.rn.f32x2 %0, %1, %2, %3;" : "=l"(d) : "l"(a), "l"(b), "l"(d));
}

// ---------------- tiled SGEMM: 128x128 block tile, BK=16, 8x8/thread ------
// MODE 0: G   = gather(X) @ Wg[e]            (K=1024, N=2816)
// MODE 1: U   = gather(X) @ Wu[e]; ACT = silu(G) * U
// MODE 2: Y   = ACT @ Wd[e]                  (K=2816, N=1024)
#define BM 128
#define BN 128
#define BK 16

template <int MODE>
__global__ __launch_bounds__(256, 2)
void gemm_kernel(const float* __restrict__ X, const float* __restrict__ W) {
    constexpr int KD = (MODE == 2) ? HDIM : DMODEL;
    constexpr int ND = (MODE == 2) ? DMODEL : HDIM;

    const int e  = blockIdx.z;
    const int m0 = blockIdx.y * BM;
    if (m0 >= g_count[e]) return;     // whole tile beyond this expert's load
    const int n0 = blockIdx.x * BN;
    const float* Bw = W + (size_t)e * KD * ND;   // W[e] is row-major [K, N]

    __shared__ float As[BK][BM];      // A stored k-major (transposed)
    __shared__ float Bs[BK][BN];
    __shared__ const float* rowptr[BM];

    const int tid = threadIdx.x;
    if (tid < BM) {
        int slot = e * CAP + m0 + tid;
        if (MODE == 2) {
            rowptr[tid] = g_ACT + (size_t)slot * HDIM;
        } else {
            int tok = g_token_of_slot[slot];
            rowptr[tid] = (tok >= 0) ? (X + (size_t)tok * DMODEL) : nullptr;
        }
    }
    __syncthreads();

    const int tx = tid & 15, ty = tid >> 4;
    const int r0 = ty * 8, c0 = tx * 8;

    unsigned long long acc[8][4];
#pragma unroll
    for (int i = 0; i < 8; i++)
#pragma unroll
        for (int j = 0; j < 4; j++) acc[i][j] = 0ULL;

    for (int k0 = 0; k0 < KD; k0 += BK) {
        // ---- load A tile (BM x BK), store transposed into As[k][m]
#pragma unroll
        for (int it = 0; it < 2; it++) {
            int i = tid + it * 256;       // 0..511 float4 chunks
            int m = i >> 2;
            int kq = (i & 3) * 4;
            const float* rp = rowptr[m];
            float4 v = make_float4(0.f, 0.f, 0.f, 0.f);
            if (rp) v = *(const float4*)(rp + k0 + kq);
            As[kq + 0][m] = v.x;
            As[kq + 1][m] = v.y;
            As[kq + 2][m] = v.z;
            As[kq + 3][m] = v.w;
        }
        // ---- load B tile (BK x BN), coalesced
#pragma unroll
        for (int it = 0; it < 2; it++) {
            int i = tid + it * 256;       // 0..511 float4 chunks
            int kk = i >> 5;
            int c  = (i & 31) * 4;
            *(float4*)&Bs[kk][c] =
                *(const float4*)(Bw + (size_t)(k0 + kk) * ND + n0 + c);
        }
        __syncthreads();

#pragma unroll
        for (int k = 0; k < BK; k++) {
            float a[8];
            *(float4*)&a[0] = *(const float4*)&As[k][r0];
            *(float4*)&a[4] = *(const float4*)&As[k][r0 + 4];
            unsigned long long b2[4];
            ulonglong2 bv0 = *(const ulonglong2*)&Bs[k][c0];
            ulonglong2 bv1 = *(const ulonglong2*)&Bs[k][c0 + 4];
            b2[0] = bv0.x; b2[1] = bv0.y; b2[2] = bv1.x; b2[3] = bv1.y;
#pragma unroll
            for (int i = 0; i < 8; i++) {
                unsigned long long a2 = pack2(a[i], a[i]);
#pragma unroll
                for (int j = 0; j < 4; j++) fma2(acc[i][j], a2, b2[j]);
            }
        }
        __syncthreads();
    }

    // ---- epilogue
#pragma unroll
    for (int i = 0; i < 8; i++) {
        size_t gslot = (size_t)(e * CAP + m0 + r0 + i);
        float out[8];
#pragma unroll
        for (int j = 0; j < 4; j++) unpack2(acc[i][j], out[2 * j], out[2 * j + 1]);

        if (MODE == 0) {
            float* dst = g_G + gslot * HDIM + n0 + c0;
            *(float4*)dst       = *(float4*)&out[0];
            *(float4*)(dst + 4) = *(float4*)&out[4];
        } else if (MODE == 1) {
            const float* gp = g_G + gslot * HDIM + n0 + c0;
            float4 gv0 = *(const float4*)gp;
            float4 gv1 = *(const float4*)(gp + 4);
            float gg[8] = {gv0.x, gv0.y, gv0.z, gv0.w, gv1.x, gv1.y, gv1.z, gv1.w};
            float av[8];
#pragma unroll
            for (int j = 0; j < 8; j++) {
                float s = gg[j] / (1.f + __expf(-gg[j]));   // silu
                av[j] = s * out[j];
            }
            float* dst = g_ACT + gslot * HDIM + n0 + c0;
            *(float4*)dst       = *(float4*)&av[0];
            *(float4*)(dst + 4) = *(float4*)&av[4];
        } else {
            float* dst = g_Y + gslot * DMODEL + n0 + c0;
            *(float4*)dst       = *(float4*)&out[0];
            *(float4*)(dst + 4) = *(float4*)&out[4];
        }
    }
}

// ---------------- gather back, scale by routing score, passthrough drops ---
__global__ void scatter_kernel(const float* __restrict__ x,
                               const float* __restrict__ scores,
                               float* __restrict__ out) {
    int t = blockIdx.x;
    int i = threadIdx.x;               // 0..255, one float4 each (d=1024)
    int slot = g_slot_of_token[t];
    float4 v;
    if (slot < SLOTS) {
        v = *(const float4*)(g_Y + (size_t)slot * DMODEL + i * 4);
        float s = scores[t];
        v.x *= s; v.y *= s; v.z *= s; v.w *= s;
    } else {
        v = *(const float4*)(x + (size_t)t * DMODEL + i * 4);
    }
    *(float4*)(out + (size_t)t * DMODEL + i * 4) = v;
}

// ---------------------------------------------------------------------------
extern "C" void kernel_launch(void* const* d_in, const int* in_sizes, int n_in,
                              void* d_out, int out_size) {
    const float* x      = (const float*)d_in[0];
    const int*   idxw   = (const int*)d_in[1];     // int32 or int64 words, detected
    const float* scores = (const float*)d_in[2];
    const float* Wg     = (const float*)d_in[3];
    const float* Wu     = (const float*)d_in[4];
    const float* Wd     = (const float*)d_in[5];
    float*       out    = (float*)d_out;

    route_kernel<<<1, 256>>>(idxw);

    dim3 block(256);
    dim3 grid_gu(HDIM / BN, CAP / BM, NEXP);    // (22, 10, 8)
    gemm_kernel<0><<<grid_gu, block>>>(x, Wg);
    gemm_kernel<1><<<grid_gu, block>>>(x, Wu);

    dim3 grid_d(DMODEL / BN, CAP / BM, NEXP);   // (8, 10, 8)
    gemm_kernel<2><<<grid_d, block>>>(nullptr, Wd);

    scatter_kernel<<<N_TOK, 256>>>(x, scores, out);
}

// round 7
// speedup vs baseline: 2.1164x; 2.1164x over previous
#include <cuda_runtime.h>
#include <cuda_bf16.h>
#include <cstdint>

// Problem constants
#define N_TOK  8192
#define DMODEL 1024
#define NEXP   8
#define HDIM   2816
#define CAP    1280
#define SLOTS  (NEXP * CAP)          // 10240

// ---------------- device scratch (~200 MB total, below proven 272 MB) ------
__device__ int g_slot_of_token[N_TOK];
__device__ int g_token_of_slot[SLOTS];
__device__ int g_count[NEXP];
__device__ __align__(256) __nv_bfloat16 g_xh [(size_t)SLOTS * DMODEL];   // 21MB
__device__ __align__(256) __nv_bfloat16 g_xl [(size_t)SLOTS * DMODEL];   // 21MB
__device__ __align__(256) __nv_bfloat16 g_acth[(size_t)SLOTS * HDIM];    // 58MB
__device__ __align__(256) __nv_bfloat16 g_actl[(size_t)SLOTS * HDIM];    // 58MB
__device__ __align__(256) float g_Y[(size_t)SLOTS * DMODEL];             // 42MB

#define MMA16816(d, a, b0, b1) \
    asm volatile("mma.sync.aligned.m16n8k16.row.col.f32.bf16.bf16.f32 " \
                 "{%0,%1,%2,%3}, {%4,%5,%6,%7}, {%8,%9}, {%0,%1,%2,%3};" \
                 : "+f"((d)[0]), "+f"((d)[1]), "+f"((d)[2]), "+f"((d)[3]) \
                 : "r"((a)[0]), "r"((a)[1]), "r"((a)[2]), "r"((a)[3]), \
                   "r"(b0), "r"(b1))

// split two fp32 into packed bf16x2 hi and lo (lo = residual)
__device__ __forceinline__ void split2(float f0, float f1,
                                       uint32_t& hi, uint32_t& lo) {
    __nv_bfloat16 h0 = __float2bfloat16_rn(f0);
    __nv_bfloat16 h1 = __float2bfloat16_rn(f1);
    __nv_bfloat16 l0 = __float2bfloat16_rn(f0 - __bfloat162float(h0));
    __nv_bfloat16 l1 = __float2bfloat16_rn(f1 - __bfloat162float(h1));
    __nv_bfloat162 hp = __halves2bfloat162(h0, h1);
    __nv_bfloat162 lp = __halves2bfloat162(l0, l1);
    hi = *(uint32_t*)&hp; lo = *(uint32_t*)&lp;
}

// ---------------- routing (dtype-adaptive int32/int64) ----------------------
__global__ void route_kernel(const int* __restrict__ idxw) {
    __shared__ int s_any;
    int tid = threadIdx.x;
    if (tid == 0) s_any = 0;
    for (int s = tid; s < SLOTS; s += 256) g_token_of_slot[s] = -1;
    __syncthreads();
    int local = 0;
    for (int i = 2 * tid + 1; i < N_TOK; i += 512) local |= idxw[i];
    if (local) atomicOr(&s_any, 1);
    __syncthreads();
    const int stride = s_any ? 1 : 2;
    int warp = tid >> 5, lane = tid & 31;
    if (warp < NEXP) {
        int e = warp, cnt = 0;
        for (int base = 0; base < N_TOK; base += 32) {
            int t = base + lane;
            int ei = idxw[t * stride];
            bool m = (ei == e);
            unsigned mask = __ballot_sync(0xffffffffu, m);
            if (m) {
                int pos = cnt + __popc(mask & ((1u << lane) - 1u));
                if (pos < CAP) {
                    g_slot_of_token[t] = e * CAP + pos;
                    g_token_of_slot[e * CAP + pos] = t;
                } else {
                    g_slot_of_token[t] = SLOTS;
                }
            }
            cnt += __popc(mask);
        }
        if (lane == 0) g_count[e] = (cnt < CAP) ? cnt : CAP;
    }
}

// ---------------- gather tokens into split bf16 slot buffer ----------------
__global__ void gather_kernel(const float* __restrict__ x) {
    int s = blockIdx.x;
    int tok = g_token_of_slot[s];
    int i = threadIdx.x;              // 0..255 -> float4
    float4 v = make_float4(0.f, 0.f, 0.f, 0.f);
    if (tok >= 0) v = *(const float4*)(x + (size_t)tok * DMODEL + i * 4);
    uint32_t h01, l01, h23, l23;
    split2(v.x, v.y, h01, l01);
    split2(v.z, v.w, h23, l23);
    uint2 hv = make_uint2(h01, h23), lv = make_uint2(l01, l23);
    *(uint2*)(g_xh + (size_t)s * DMODEL + i * 4) = hv;
    *(uint2*)(g_xl + (size_t)s * DMODEL + i * 4) = lv;
}

// ---------------- fused gate+up GEMM (mma.sync, split bf16) ----------------
// BM=128, BN=64, BK=32; 256 threads = 8 warps (4m x 2n), warp tile 32x32.
// A: precomputed split bf16 (g_xh/g_xl). B: fp32 W tiles staged in smem,
// converted to hi/lo fragments in registers. D = Ah*Bh + Ah*Bl + Al*Bh.
#define BM 128
#define BN 64
#define BK 32
#define APAD 40   // bf16 row stride for A tiles
#define BPAD 68   // f32 row stride for B tiles

__global__ void __launch_bounds__(256) gemm_gu_kernel(
        const float* __restrict__ Wg, const float* __restrict__ Wu) {
    __shared__ __align__(16) __nv_bfloat16 sAh[BM][APAD];
    __shared__ __align__(16) __nv_bfloat16 sAl[BM][APAD];
    __shared__ __align__(16) float sBg[BK][BPAD];
    __shared__ __align__(16) float sBu[BK][BPAD];

    const int e  = blockIdx.z;
    const int m0 = blockIdx.y * BM;
    if (m0 >= g_count[e]) return;
    const int n0 = blockIdx.x * BN;

    const size_t abase = (size_t)(e * CAP + m0) * DMODEL;
    const float* Bg = Wg + (size_t)e * DMODEL * HDIM;
    const float* Bu = Wu + (size_t)e * DMODEL * HDIM;

    const int tid  = threadIdx.x;
    const int lane = tid & 31, warp = tid >> 5;
    const int wm = warp >> 1, wn = warp & 1;
    const int fr = lane >> 2;
    const int fc = (lane & 3) * 2;

    // A loads: uint4 = 8 bf16; 128 rows x 4 chunks = 512 / 256 thr = 2 each
    const int ar0 = tid >> 2, ac0 = (tid & 3) * 8;
    const int ar1 = ar0 + 64;
    // B loads: float4; 32 rows x 16 chunks = 512 / 256 thr = 2 each
    const int br0 = tid >> 4, bc0 = (tid & 15) * 4;
    const int br1 = br0 + 16;

    uint4 pah0, pah1, pal0, pal1;
    float4 pbg0, pbg1, pbu0, pbu1;
    auto prefetch = [&](int c) {
        const int k0 = c * BK;
        pah0 = *(const uint4*)(g_xh + abase + (size_t)ar0 * DMODEL + k0 + ac0);
        pal0 = *(const uint4*)(g_xl + abase + (size_t)ar0 * DMODEL + k0 + ac0);
        pah1 = *(const uint4*)(g_xh + abase + (size_t)ar1 * DMODEL + k0 + ac0);
        pal1 = *(const uint4*)(g_xl + abase + (size_t)ar1 * DMODEL + k0 + ac0);
        pbg0 = *(const float4*)(Bg + (size_t)(k0 + br0) * HDIM + n0 + bc0);
        pbg1 = *(const float4*)(Bg + (size_t)(k0 + br1) * HDIM + n0 + bc0);
        pbu0 = *(const float4*)(Bu + (size_t)(k0 + br0) * HDIM + n0 + bc0);
        pbu1 = *(const float4*)(Bu + (size_t)(k0 + br1) * HDIM + n0 + bc0);
    };

    float accG[2][4][4], accU[2][4][4];
#pragma unroll
    for (int i = 0; i < 2; i++)
#pragma unroll
        for (int j = 0; j < 4; j++)
#pragma unroll
            for (int q = 0; q < 4; q++) { accG[i][j][q] = 0.f; accU[i][j][q] = 0.f; }

    const int kchunks = DMODEL / BK;   // 32
    prefetch(0);

    for (int c = 0; c < kchunks; c++) {
        __syncthreads();
        *(uint4*)&sAh[ar0][ac0] = pah0;
        *(uint4*)&sAl[ar0][ac0] = pal0;
        *(uint4*)&sAh[ar1][ac0] = pah1;
        *(uint4*)&sAl[ar1][ac0] = pal1;
        *(float4*)&sBg[br0][bc0] = pbg0;
        *(float4*)&sBg[br1][bc0] = pbg1;
        *(float4*)&sBu[br0][bc0] = pbu0;
        *(float4*)&sBu[br1][bc0] = pbu1;
        __syncthreads();
        if (c + 1 < kchunks) prefetch(c + 1);

#pragma unroll
        for (int ks = 0; ks < 2; ks++) {
            const int ko = ks * 16 + fc;
            uint32_t ah[2][4], al[2][4];
#pragma unroll
            for (int mt = 0; mt < 2; mt++) {
                const int mr = wm * 32 + mt * 16 + fr;
                ah[mt][0] = *(const uint32_t*)&sAh[mr    ][ko    ];
                ah[mt][1] = *(const uint32_t*)&sAh[mr + 8][ko    ];
                ah[mt][2] = *(const uint32_t*)&sAh[mr    ][ko + 8];
                ah[mt][3] = *(const uint32_t*)&sAh[mr + 8][ko + 8];
                al[mt][0] = *(const uint32_t*)&sAl[mr    ][ko    ];
                al[mt][1] = *(const uint32_t*)&sAl[mr + 8][ko    ];
                al[mt][2] = *(const uint32_t*)&sAl[mr    ][ko + 8];
                al[mt][3] = *(const uint32_t*)&sAl[mr + 8][ko + 8];
            }
#pragma unroll
            for (int nt = 0; nt < 4; nt++) {
                const int nr = wn * 32 + nt * 8 + fr;
                uint32_t bh0, bl0, bh1, bl1;
                // gate
                split2(sBg[ko][nr],     sBg[ko + 1][nr], bh0, bl0);
                split2(sBg[ko + 8][nr], sBg[ko + 9][nr], bh1, bl1);
#pragma unroll
                for (int mt = 0; mt < 2; mt++) {
                    MMA16816(accG[mt][nt], ah[mt], bh0, bh1);
                    MMA16816(accG[mt][nt], ah[mt], bl0, bl1);
                    MMA16816(accG[mt][nt], al[mt], bh0, bh1);
                }
                // up
                split2(sBu[ko][nr],     sBu[ko + 1][nr], bh0, bl0);
                split2(sBu[ko + 8][nr], sBu[ko + 9][nr], bh1, bl1);
#pragma unroll
                for (int mt = 0; mt < 2; mt++) {
                    MMA16816(accU[mt][nt], ah[mt], bh0, bh1);
                    MMA16816(accU[mt][nt], ah[mt], bl0, bl1);
                    MMA16816(accU[mt][nt], al[mt], bh0, bh1);
                }
            }
        }
    }

    // ---- epilogue: act = silu(g) * u -> split bf16
#pragma unroll
    for (int mt = 0; mt < 2; mt++) {
#pragma unroll
        for (int half = 0; half < 2; half++) {
            const size_t slotrow =
                (size_t)(e * CAP + m0 + wm * 32 + mt * 16 + half * 8 + fr);
#pragma unroll
            for (int nt = 0; nt < 4; nt++) {
                const int gcol = n0 + wn * 32 + nt * 8 + fc;
                float gg0 = accG[mt][nt][half * 2 + 0];
                float gg1 = accG[mt][nt][half * 2 + 1];
                float uu0 = accU[mt][nt][half * 2 + 0];
                float uu1 = accU[mt][nt][half * 2 + 1];
                float a0 = (gg0 / (1.f + __expf(-gg0))) * uu0;
                float a1 = (gg1 / (1.f + __expf(-gg1))) * uu1;
                uint32_t hi, lo;
                split2(a0, a1, hi, lo);
                *(uint32_t*)&g_acth[slotrow * HDIM + gcol] = hi;
                *(uint32_t*)&g_actl[slotrow * HDIM + gcol] = lo;
            }
        }
    }
}

// ---------------- down GEMM: Y = ACT @ Wd[e] --------------------------------
__global__ void __launch_bounds__(256) gemm_down_kernel(
        const float* __restrict__ Wd) {
    __shared__ __align__(16) __nv_bfloat16 sAh[BM][APAD];
    __shared__ __align__(16) __nv_bfloat16 sAl[BM][APAD];
    __shared__ __align__(16) float sB[BK][BPAD];

    const int e  = blockIdx.z;
    const int m0 = blockIdx.y * BM;
    if (m0 >= g_count[e]) return;
    const int n0 = blockIdx.x * BN;

    const size_t abase = (size_t)(e * CAP + m0) * HDIM;
    const float* Bd = Wd + (size_t)e * HDIM * DMODEL;

    const int tid  = threadIdx.x;
    const int lane = tid & 31, warp = tid >> 5;
    const int wm = warp >> 1, wn = warp & 1;
    const int fr = lane >> 2;
    const int fc = (lane & 3) * 2;

    const int ar0 = tid >> 2, ac0 = (tid & 3) * 8;
    const int ar1 = ar0 + 64;
    const int br0 = tid >> 4, bc0 = (tid & 15) * 4;
    const int br1 = br0 + 16;

    uint4 pah0, pah1, pal0, pal1;
    float4 pb0, pb1;
    auto prefetch = [&](int c) {
        const int k0 = c * BK;
        pah0 = *(const uint4*)(g_acth + abase + (size_t)ar0 * HDIM + k0 + ac0);
        pal0 = *(const uint4*)(g_actl + abase + (size_t)ar0 * HDIM + k0 + ac0);
        pah1 = *(const uint4*)(g_acth + abase + (size_t)ar1 * HDIM + k0 + ac0);
        pal1 = *(const uint4*)(g_actl + abase + (size_t)ar1 * HDIM + k0 + ac0);
        pb0 = *(const float4*)(Bd + (size_t)(k0 + br0) * DMODEL + n0 + bc0);
        pb1 = *(const float4*)(Bd + (size_t)(k0 + br1) * DMODEL + n0 + bc0);
    };

    float acc[2][4][4];
#pragma unroll
    for (int i = 0; i < 2; i++)
#pragma unroll
        for (int j = 0; j < 4; j++)
#pragma unroll
            for (int q = 0; q < 4; q++) acc[i][j][q] = 0.f;

    const int kchunks = HDIM / BK;   // 88
    prefetch(0);

    for (int c = 0; c < kchunks; c++) {
        __syncthreads();
        *(uint4*)&sAh[ar0][ac0] = pah0;
        *(uint4*)&sAl[ar0][ac0] = pal0;
        *(uint4*)&sAh[ar1][ac0] = pah1;
        *(uint4*)&sAl[ar1][ac0] = pal1;
        *(float4*)&sB[br0][bc0] = pb0;
        *(float4*)&sB[br1][bc0] = pb1;
        __syncthreads();
        if (c + 1 < kchunks) prefetch(c + 1);

#pragma unroll
        for (int ks = 0; ks < 2; ks++) {
            const int ko = ks * 16 + fc;
            uint32_t ah[2][4], al[2][4];
#pragma unroll
            for (int mt = 0; mt < 2; mt++) {
                const int mr = wm * 32 + mt * 16 + fr;
                ah[mt][0] = *(const uint32_t*)&sAh[mr    ][ko    ];
                ah[mt][1] = *(const uint32_t*)&sAh[mr + 8][ko    ];
                ah[mt][2] = *(const uint32_t*)&sAh[mr    ][ko + 8];
                ah[mt][3] = *(const uint32_t*)&sAh[mr + 8][ko + 8];
                al[mt][0] = *(const uint32_t*)&sAl[mr    ][ko    ];
                al[mt][1] = *(const uint32_t*)&sAl[mr + 8][ko    ];
                al[mt][2] = *(const uint32_t*)&sAl[mr    ][ko + 8];
                al[mt][3] = *(const uint32_t*)&sAl[mr + 8][ko + 8];
            }
#pragma unroll
            for (int nt = 0; nt < 4; nt++) {
                const int nr = wn * 32 + nt * 8 + fr;
                uint32_t bh0, bl0, bh1, bl1;
                split2(sB[ko][nr],     sB[ko + 1][nr], bh0, bl0);
                split2(sB[ko + 8][nr], sB[ko + 9][nr], bh1, bl1);
#pragma unroll
                for (int mt = 0; mt < 2; mt++) {
                    MMA16816(acc[mt][nt], ah[mt], bh0, bh1);
                    MMA16816(acc[mt][nt], ah[mt], bl0, bl1);
                    MMA16816(acc[mt][nt], al[mt], bh0, bh1);
                }
            }
        }
    }

#pragma unroll
    for (int mt = 0; mt < 2; mt++) {
#pragma unroll
        for (int half = 0; half < 2; half++) {
            const size_t slotrow =
                (size_t)(e * CAP + m0 + wm * 32 + mt * 16 + half * 8 + fr);
#pragma unroll
            for (int nt = 0; nt < 4; nt++) {
                const int gcol = n0 + wn * 32 + nt * 8 + fc;
                *(float2*)&g_Y[slotrow * DMODEL + gcol] =
                    make_float2(acc[mt][nt][half * 2 + 0],
                                acc[mt][nt][half * 2 + 1]);
            }
        }
    }
}

// ---------------- scatter back -----------------------------------------------
__global__ void scatter_kernel(const float* __restrict__ x,
                               const float* __restrict__ scores,
                               float* __restrict__ out) {
    int t = blockIdx.x;
    int i = threadIdx.x;
    int slot = g_slot_of_token[t];
    float4 v;
    if (slot < SLOTS) {
        v = *(const float4*)(g_Y + (size_t)slot * DMODEL + i * 4);
        float s = scores[t];
        v.x *= s; v.y *= s; v.z *= s; v.w *= s;
    } else {
        v = *(const float4*)(x + (size_t)t * DMODEL + i * 4);
    }
    *(float4*)(out + (size_t)t * DMODEL + i * 4) = v;
}

// -----------------------------------------------------------------------------
extern "C" void kernel_launch(void* const* d_in, const int* in_sizes, int n_in,
                              void* d_out, int out_size) {
    const float* x      = (const float*)d_in[0];
    const int*   idxw   = (const int*)d_in[1];
    const float* scores = (const float*)d_in[2];
    const float* Wg     = (const float*)d_in[3];
    const float* Wu     = (const float*)d_in[4];
    const float* Wd     = (const float*)d_in[5];
    float*       out    = (float*)d_out;

    route_kernel<<<1, 256>>>(idxw);
    gather_kernel<<<SLOTS, 256>>>(x);

    gemm_gu_kernel<<<dim3(HDIM / BN, CAP / BM, NEXP), 256>>>(Wg, Wu);
    gemm_down_kernel<<<dim3(DMODEL / BN, CAP / BM, NEXP), 256>>>(Wd);

    scatter_kernel<<<N_TOK, 256>>>(x, scores, out);
}